// round 10
// baseline (speedup 1.0000x reference)
#include <cuda_runtime.h>
#include <math_constants.h>
#include <cfloat>

// Problem constants (B=2, L=256, A=12, C=32, K=30)
#define NB 2
#define NL 256
#define NA 12
#define NATOM 3072          // NL*NA
#define NROWS (NB*NATOM)    // 6144
#define NC 32
#define KNB 30
#define BIGD 1000000.0f
#define EMPTY_BITS 0xFFFFFFFFu
#define POISON 1.0e18f               // masked-atom coordinate (d2 -> 3e36 exactly)

// Output layout (all float32, concatenated in reference tuple order)
#define O_COORDS 0                       // (B, NATOM, 3)  -> 18432
#define O_MASK   (NB*NATOM*3)            // (B, NATOM)     -> 6144
#define O_ENC    (O_MASK + NB*NATOM)     // (B, NATOM, 32) -> 196608
#define O_DIST   (O_ENC + NB*NATOM*NC)   // (B, NATOM, 30) -> 184320
#define O_IDX    (O_DIST + NB*NATOM*KNB) // (B, NATOM, 30) -> 184320

#define WARPS 6              // row slots per block
#define THR (WARPS * 32)     // 192
#define TPAD 97              // padded key-slice stride (32*97 floats per warp)
#define NT 96                // candidates per lane/column (3072/32)

__device__ float4 g_atoms[NB * NATOM];   // poisoned {x,y,z,mask}, 98 KB
__device__ float  g_A[NB * NC];          // rstd * scale
__device__ float  g_B[NB * NC];          // shift - mean * rstd * scale
__device__ int    g_rows[NROWS];         // compacted: active rows first
__device__ int    g_nact;                // number of active rows

// ---------------------------------------------------------------------------
// Prep: block 0 computes coefs + row compaction; all blocks poison the atom
// table, copy coords, and write the mask output.
// ---------------------------------------------------------------------------
#define PREP_BLOCKS 25
__global__ void prep_kernel(const float* __restrict__ coords,
                            const int* __restrict__ mask,
                            const float* __restrict__ T,
                            const float* __restrict__ scale,
                            const float* __restrict__ shift,
                            float* __restrict__ out) {
    int tid = threadIdx.x;     // 256

    if (blockIdx.x == 0) {
        // ---- graph-norm coefficients ----
        __shared__ float sred[NB][8];
        int warp = tid >> 5, lane = tid & 31;
        int s0 = __reduce_add_sync(0xffffffffu, mask[tid]);
        int s1 = __reduce_add_sync(0xffffffffu, mask[NL + tid]);
        if (lane == 0) { sred[0][warp] = (float)s0; sred[1][warp] = (float)s1; }
        __syncthreads();
        if (tid < NB * NC) {
            int b = tid >> 5, c = tid & 31;
            float nm = 0.f;
            #pragma unroll
            for (int i = 0; i < 8; ++i) nm += sred[b][i];
            float colsum = 0.f, tv[NA];
            #pragma unroll
            for (int a = 0; a < NA; ++a) { tv[a] = T[a * NC + c]; colsum += tv[a]; }
            float cntA = nm * (float)NA;
            float cnt  = fmaxf(cntA, 1.0f);
            float mean = (nm * colsum) / cnt;
            float ssqm = 0.f;
            #pragma unroll
            for (int a = 0; a < NA; ++a) {
                float d = tv[a] - mean;
                ssqm = fmaf(d, d, ssqm);
            }
            float ssq  = nm * ssqm + ((float)NATOM - cntA) * mean * mean;
            float rstd = rsqrtf(ssq / cnt + 1e-5f);
            float Ac   = rstd * scale[c];
            g_A[tid] = Ac;
            g_B[tid] = shift[c] - mean * Ac;
        }

        // ---- row compaction: scan over 512 residues (2 per thread) ----
        __shared__ int buf[2][256];
        int r0 = 2 * tid, r1 = 2 * tid + 1;
        int m0 = mask[r0 < NL ? r0 : (NL + r0 - NL)];   // residues are batch-major
        // simpler: residue r -> mask[(r>>8)*NL + (r&255)]? NL=256 so mask[r] works
        m0 = mask[r0];
        int m1 = mask[r1];
        int pairsum = m0 + m1;
        buf[0][tid] = pairsum;
        __syncthreads();
        int src = 0;
        #pragma unroll
        for (int off = 1; off < 256; off <<= 1) {
            int v = buf[src][tid] + ((tid >= off) ? buf[src][tid - off] : 0);
            buf[1 - src][tid] = v;
            src ^= 1;
            __syncthreads();
        }
        int incl = buf[src][tid];             // inclusive prefix of pair sums
        int nA = buf[src][255];               // total active residues
        if (tid == 0) g_nact = nA * NA;

        int pre0 = incl - pairsum;            // exclusive prefix at residue r0
        int pre1 = pre0 + m0;                 // exclusive prefix at residue r1
        // residue r -> slots: active at 12*pre(r); masked at 12*(nA + (r - pre(r)))
        int base0 = m0 ? (NA * pre0) : (NA * (nA + (r0 - pre0)));
        int base1 = m1 ? (NA * pre1) : (NA * (nA + (r1 - pre1)));
        #pragma unroll
        for (int a = 0; a < NA; ++a) {
            g_rows[base0 + a] = r0 * NA + a;
            g_rows[base1 + a] = r1 * NA + a;
        }
    }

    // ---- all blocks: poison atoms, copy coords, write mask output ----
    for (int a = blockIdx.x * 256 + tid; a < NROWS; a += PREP_BLOCKS * 256) {
        int b = a / NATOM;
        int j = a - b * NATOM;
        int m = mask[b * NL + j / NA];
        float4 v;
        float x = coords[a * 3 + 0], y = coords[a * 3 + 1], z = coords[a * 3 + 2];
        v.x = m ? x : POISON;
        v.y = m ? y : POISON;
        v.z = m ? z : POISON;
        v.w = (float)m;
        g_atoms[a] = v;
        out[O_MASK + a] = (float)m;
    }
    for (int i = blockIdx.x * 256 + tid; i < NROWS * 3; i += PREP_BLOCKS * 256) {
        out[O_COORDS + i] = coords[i];
    }
}

// ---------------------------------------------------------------------------
// KNN: warp-per-slot over compacted rows. Active slots run the R8 engine
// (register top-2 heads + smem d2 cache refill); masked slots emit constant
// outputs and retire immediately.
// ---------------------------------------------------------------------------
__global__ void __launch_bounds__(THR, 3)
knn_kernel(const float* __restrict__ T,
           float* __restrict__ out) {
    extern __shared__ float s_d2[];                  // WARPS*32*97 = 74496 B

    int tid  = threadIdx.x;
    int warp = tid >> 5;
    int lane = tid & 31;

    int slot = blockIdx.x * WARPS + warp;
    int row  = g_rows[slot];
    int b    = row / NATOM;
    int ib   = row - b * NATOM;

    float* dist_out = out + O_DIST + row * KNB;
    float* idx_out  = out + O_IDX  + row * KNB;

    if (slot >= g_nact) {                     // masked row -> constant outputs
        out[O_ENC + row * NC + lane] = 0.0f;
        if (lane < KNB) {
            dist_out[lane] = BIGD;
            idx_out[lane]  = 0.0f;
        }
        return;
    }

    const float4* At = g_atoms + b * NATOM;
    float4 q = __ldg(&At[ib]);

    // encode for active row (q.w == 1 guaranteed)
    {
        int ty = ib % NA;
        out[O_ENC + row * NC + lane] =
            fmaf(__ldg(&T[ty * NC + lane]), g_A[b * NC + lane], g_B[b * NC + lane]);
    }

    float* my = s_d2 + warp * (32 * TPAD);

    // ---- phase A: keys -> smem cache + branchless per-lane top-2 heads ----
    unsigned v0 = EMPTY_BITS, v1 = EMPTY_BITS;
    int i0 = 0, i1 = 0;
    #pragma unroll 8
    for (int t = 0; t < NT; ++t) {
        float4 a = __ldg(&At[t * 32 + lane]);
        float dx = q.x - a.x, dy = q.y - a.y, dz = q.z - a.z;
        float d2 = fmaf(dx, dx, fmaf(dy, dy, dz * dz));
        my[lane * TPAD + t] = d2;
        unsigned kb = __float_as_uint(d2);    // d2 >= 0 -> bits order-preserving
        int j = t * 32 + lane;
        bool lt1 = kb < v1;
        bool lt0 = kb < v0;                   // strict < keeps lowest-index tie order
        v1 = lt1 ? (lt0 ? v0 : kb) : v1;
        i1 = lt1 ? (lt0 ? i0 : j ) : i1;
        v0 = lt0 ? kb : v0;
        i0 = lt0 ? j  : i0;
    }

    // ---- extract-min x30 from the 32 lane-heads ----
    unsigned rvb = 0; int rj = 0;             // lane p holds pass-p result
    #pragma unroll 1
    for (int p = 0; p < KNB; ++p) {
        unsigned mvb = __reduce_min_sync(0xffffffffu, v0);
        unsigned cj  = (v0 == mvb) ? (unsigned)i0 : 0xFFFFFFFFu;
        unsigned mj  = __reduce_min_sync(0xffffffffu, cj);
        if (lane == p) { rvb = mvb; rj = (int)mj; }

        if (p < KNB - 1) {
            int w  = (int)(mj & 31u);
            int tm = (int)(mj >> 5);
            if (lane == w) {                  // owner: invalidate popped slot + pop
                my[w * TPAD + tm] = CUDART_INF_F;
                v0 = v1; i0 = i1; v1 = EMPTY_BITS;
            }
            bool empty = (lane == w) && (v0 == EMPTY_BITS);
            if (__ballot_sync(0xffffffffu, empty)) {
                // refill owner's head: cooperative 3-LDS rescan of column w
                __syncwarp();                 // make prior STS invalidations visible
                unsigned nvb = EMPTY_BITS;
                int nj = 0;
                #pragma unroll
                for (int s = 0; s < 3; ++s) {
                    int t = lane + s * 32;
                    float v = my[w * TPAD + t];
                    unsigned vb = __float_as_uint(v);
                    if (vb < nvb) { nvb = vb; nj = t * 32 + w; }
                }
                unsigned nmin = __reduce_min_sync(0xffffffffu, nvb);
                unsigned ncj  = (nvb == nmin) ? (unsigned)nj : 0xFFFFFFFFu;
                unsigned nidx = __reduce_min_sync(0xffffffffu, ncj);
                if (lane == w) { v0 = nmin; i0 = (int)nidx; }
            }
        }
    }

    if (lane < KNB) {
        float d2 = __uint_as_float(rvb);
        float dv = (d2 > 1e30f) ? BIGD : sqrtf(d2 + 1e-6f);
        dist_out[lane] = dv;
        idx_out[lane]  = (float)rj;
    }
}

// ---------------------------------------------------------------------------
extern "C" void kernel_launch(void* const* d_in, const int* in_sizes, int n_in,
                              void* d_out, int out_size) {
    const float* coords = (const float*)d_in[0];   // (2,256,12,3) f32
    const int*   mask   = (const int*)d_in[1];     // (2,256) i32
    const float* emb    = (const float*)d_in[2];   // (12,32) f32
    const float* scale  = (const float*)d_in[3];   // (1,1,32) f32
    const float* shift  = (const float*)d_in[4];   // (1,1,32) f32
    float* out = (float*)d_out;

    prep_kernel<<<PREP_BLOCKS, 256>>>(coords, mask, emb, scale, shift, out);

    int smem_bytes = WARPS * 32 * TPAD * 4;        // 74496
    cudaFuncSetAttribute(knn_kernel, cudaFuncAttributeMaxDynamicSharedMemorySize,
                         smem_bytes);
    int nblocks = NROWS / WARPS;                   // 1024
    knn_kernel<<<nblocks, THR, smem_bytes>>>(emb, out);
}

// round 11
// speedup vs baseline: 1.0328x; 1.0328x over previous
#include <cuda_runtime.h>
#include <math_constants.h>
#include <cfloat>

// Problem constants (B=2, L=256, A=12, C=32, K=30)
#define NB 2
#define NL 256
#define NA 12
#define NATOM 3072          // NL*NA
#define NROWS (NB*NATOM)    // 6144
#define NC 32
#define KNB 30
#define BIGD 1000000.0f
#define EMPTY_BITS 0xFFFFFFFFu
#define POISON 1.0e18f               // masked-atom coordinate (d2 -> 3e36 exactly)

// Output layout (all float32, concatenated in reference tuple order)
#define O_COORDS 0                       // (B, NATOM, 3)  -> 18432
#define O_MASK   (NB*NATOM*3)            // (B, NATOM)     -> 6144
#define O_ENC    (O_MASK + NB*NATOM)     // (B, NATOM, 32) -> 196608
#define O_DIST   (O_ENC + NB*NATOM*NC)   // (B, NATOM, 30) -> 184320
#define O_IDX    (O_DIST + NB*NATOM*KNB) // (B, NATOM, 30) -> 184320

#define WARPS 4              // row slots per block
#define THR (WARPS * 32)     // 128

__device__ float4 g_atoms[NB * NATOM];   // poisoned {x,y,z,mask}, 98 KB
__device__ float  g_A[NB * NC];          // rstd * scale
__device__ float  g_B[NB * NC];          // shift - mean * rstd * scale
__device__ int    g_rows[NROWS];         // compacted: active rows first
__device__ int    g_nact;                // number of active rows

// ---------------------------------------------------------------------------
// Prep: block 0 computes coefs + row compaction; all blocks poison atoms.
// ---------------------------------------------------------------------------
#define PREP_BLOCKS 48
__global__ void prep_kernel(const float* __restrict__ coords,
                            const int* __restrict__ mask,
                            const float* __restrict__ T,
                            const float* __restrict__ scale,
                            const float* __restrict__ shift) {
    int tid = threadIdx.x;     // 256

    if (blockIdx.x == 0) {
        // ---- graph-norm coefficients ----
        __shared__ float sred[NB][8];
        int warp = tid >> 5, lane = tid & 31;
        int s0 = __reduce_add_sync(0xffffffffu, mask[tid]);
        int s1 = __reduce_add_sync(0xffffffffu, mask[NL + tid]);
        if (lane == 0) { sred[0][warp] = (float)s0; sred[1][warp] = (float)s1; }
        __syncthreads();
        if (tid < NB * NC) {
            int b = tid >> 5, c = tid & 31;
            float nm = 0.f;
            #pragma unroll
            for (int i = 0; i < 8; ++i) nm += sred[b][i];
            float colsum = 0.f, tv[NA];
            #pragma unroll
            for (int a = 0; a < NA; ++a) { tv[a] = T[a * NC + c]; colsum += tv[a]; }
            float cntA = nm * (float)NA;
            float cnt  = fmaxf(cntA, 1.0f);
            float mean = (nm * colsum) / cnt;
            float ssqm = 0.f;
            #pragma unroll
            for (int a = 0; a < NA; ++a) {
                float d = tv[a] - mean;
                ssqm = fmaf(d, d, ssqm);
            }
            float ssq  = nm * ssqm + ((float)NATOM - cntA) * mean * mean;
            float rstd = rsqrtf(ssq / cnt + 1e-5f);
            float Ac   = rstd * scale[c];
            g_A[tid] = Ac;
            g_B[tid] = shift[c] - mean * Ac;
        }

        // ---- row compaction: scan over 512 residues (2 per thread) ----
        __shared__ int buf[2][256];
        int r0 = 2 * tid, r1 = 2 * tid + 1;
        int m0 = mask[r0];
        int m1 = mask[r1];
        int pairsum = m0 + m1;
        buf[0][tid] = pairsum;
        __syncthreads();
        int src = 0;
        #pragma unroll
        for (int off = 1; off < 256; off <<= 1) {
            int v = buf[src][tid] + ((tid >= off) ? buf[src][tid - off] : 0);
            buf[1 - src][tid] = v;
            src ^= 1;
            __syncthreads();
        }
        int incl = buf[src][tid];             // inclusive prefix of pair sums
        int nA = buf[src][255];               // total active residues
        if (tid == 0) g_nact = nA * NA;

        int pre0 = incl - pairsum;            // exclusive prefix at residue r0
        int pre1 = pre0 + m0;
        int base0 = m0 ? (NA * pre0) : (NA * (nA + (r0 - pre0)));
        int base1 = m1 ? (NA * pre1) : (NA * (nA + (r1 - pre1)));
        #pragma unroll
        for (int a = 0; a < NA; ++a) {
            g_rows[base0 + a] = r0 * NA + a;
            g_rows[base1 + a] = r1 * NA + a;
        }
    }

    // ---- all blocks: poison atoms ----
    for (int a = blockIdx.x * 256 + tid; a < NROWS; a += PREP_BLOCKS * 256) {
        int b = a / NATOM;
        int j = a - b * NATOM;
        int m = mask[b * NL + j / NA];
        float4 v;
        float x = coords[a * 3 + 0], y = coords[a * 3 + 1], z = coords[a * 3 + 2];
        v.x = m ? x : POISON;
        v.y = m ? y : POISON;
        v.z = m ? z : POISON;
        v.w = (float)m;
        g_atoms[a] = v;
    }
}

// ---------------------------------------------------------------------------
// KNN: warp-per-slot over compacted rows. Zero smem. Each lane keeps TWO
// branchless top-2 streams (t<48 / t>=48). Extraction: 2 redux per pass over
// presented heads. Refill (E~0.25/row) recomputes the k-th min of the owner's
// 48-element sub-column from the global atom table.
// ---------------------------------------------------------------------------
__global__ void __launch_bounds__(THR, 8)
knn_kernel(const float* __restrict__ coords,
           const float* __restrict__ T,
           float* __restrict__ out) {
    int tid  = threadIdx.x;
    int warp = tid >> 5;
    int lane = tid & 31;

    // coords copy + mask output, grid-stride over spare threads
    {
        int i = blockIdx.x * THR + tid;
        if (i < NROWS * 3) out[O_COORDS + i] = coords[i];
        if (i < NROWS) {
            int b2 = i / NATOM;
            int n2 = i - b2 * NATOM;
            // mask value from atom table not yet guaranteed? prep ran before.
            out[O_MASK + i] = g_atoms[i].w;
            (void)b2; (void)n2;
        }
    }

    int slot = blockIdx.x * WARPS + warp;
    int row  = g_rows[slot];
    int b    = row / NATOM;
    int ib   = row - b * NATOM;

    float* dist_out = out + O_DIST + row * KNB;
    float* idx_out  = out + O_IDX  + row * KNB;

    if (slot >= g_nact) {                     // masked row -> constant outputs
        out[O_ENC + row * NC + lane] = 0.0f;
        if (lane < KNB) {
            dist_out[lane] = BIGD;
            idx_out[lane]  = 0.0f;
        }
        return;
    }

    const float4* At = g_atoms + b * NATOM;
    float4 q = __ldg(&At[ib]);

    // encode for active row
    {
        int ty = ib % NA;
        out[O_ENC + row * NC + lane] =
            fmaf(__ldg(&T[ty * NC + lane]), g_A[b * NC + lane], g_B[b * NC + lane]);
    }

    // ---- phase A: two branchless top-2 streams per lane ----
    unsigned va0 = EMPTY_BITS, va1 = EMPTY_BITS, vb0 = EMPTY_BITS, vb1 = EMPTY_BITS;
    int ia0 = 0, ia1 = 0, ib0 = 0, ib1 = 0;

    #pragma unroll 8
    for (int t = 0; t < 48; ++t) {
        float4 a = __ldg(&At[t * 32 + lane]);
        float dx = q.x - a.x, dy = q.y - a.y, dz = q.z - a.z;
        float d2 = fmaf(dx, dx, fmaf(dy, dy, dz * dz));
        unsigned kb = __float_as_uint(d2);
        int j = t * 32 + lane;
        bool lt1 = kb < va1;
        bool lt0 = kb < va0;                  // strict < keeps lowest-index ties
        va1 = lt1 ? (lt0 ? va0 : kb) : va1;
        ia1 = lt1 ? (lt0 ? ia0 : j ) : ia1;
        va0 = lt0 ? kb : va0;
        ia0 = lt0 ? j  : ia0;
    }
    #pragma unroll 8
    for (int t = 48; t < 96; ++t) {
        float4 a = __ldg(&At[t * 32 + lane]);
        float dx = q.x - a.x, dy = q.y - a.y, dz = q.z - a.z;
        float d2 = fmaf(dx, dx, fmaf(dy, dy, dz * dz));
        unsigned kb = __float_as_uint(d2);
        int j = t * 32 + lane;
        bool lt1 = kb < vb1;
        bool lt0 = kb < vb0;
        vb1 = lt1 ? (lt0 ? vb0 : kb) : vb1;
        ib1 = lt1 ? (lt0 ? ib0 : j ) : ib1;
        vb0 = lt0 ? kb : vb0;
        ib0 = lt0 ? j  : ib0;
    }

    int cA = 0, cB = 0;                       // popped counts per stream
    unsigned rvb = 0; int rj = 0;             // lane p holds pass-p result

    #pragma unroll 1
    for (int p = 0; p < KNB; ++p) {
        // presented head = min of two stream heads (tie -> stream A, lower j)
        unsigned pv = (vb0 < va0) ? vb0 : va0;
        int      pi = (vb0 < va0) ? ib0 : ia0;

        unsigned mvb = __reduce_min_sync(0xffffffffu, pv);
        unsigned cj  = (pv == mvb) ? (unsigned)pi : 0xFFFFFFFFu;
        unsigned mj  = __reduce_min_sync(0xffffffffu, cj);
        if (lane == p) { rvb = mvb; rj = (int)mj; }

        if (p < KNB - 1) {
            int w  = (int)(mj & 31u);
            int tm = (int)(mj >> 5);
            bool fromA = (tm < 48);
            bool needRefill = false;
            if (lane == w) {                  // owner pops the winning stream
                if (fromA) { va0 = va1; ia0 = ia1; va1 = EMPTY_BITS; ++cA;
                             needRefill = (va0 == EMPTY_BITS); }
                else       { vb0 = vb1; ib0 = ib1; vb1 = EMPTY_BITS; ++cB;
                             needRefill = (vb0 == EMPTY_BITS); }
            }
            if (__ballot_sync(0xffffffffu, needRefill)) {
                // rare: k-th smallest of owner's 48-elem sub-column from gmem
                int k = __shfl_sync(0xffffffffu, (fromA ? cA : cB), w) + 1;
                int tb = fromA ? 0 : 48;
                // lane reads element (tb+lane); lanes 0..15 also (tb+32+lane)
                unsigned k0, k1; int j0, j1;
                {
                    int t0 = tb + lane;
                    float4 a = __ldg(&At[t0 * 32 + w]);
                    float dx = q.x; // placeholder to keep regs tight
                    float qx = __shfl_sync(0xffffffffu, q.x, lane); // no-op
                    (void)dx; (void)qx;
                }
                {
                    int t0 = tb + lane;
                    float4 a0 = __ldg(&At[t0 * 32 + w]);
                    // distances must use the OWNER's query point:
                    float qx = __shfl_sync(0xffffffffu, q.x, w);
                    float qy = __shfl_sync(0xffffffffu, q.y, w);
                    float qz = __shfl_sync(0xffffffffu, q.z, w);
                    float dx = qx - a0.x, dy = qy - a0.y, dz = qz - a0.z;
                    float d2 = fmaf(dx, dx, fmaf(dy, dy, dz * dz));
                    k0 = __float_as_uint(d2);
                    j0 = t0 * 32 + w;
                    if (lane < 16) {
                        int t1 = tb + 32 + lane;
                        float4 a1 = __ldg(&At[t1 * 32 + w]);
                        float ex = qx - a1.x, ey = qy - a1.y, ez = qz - a1.z;
                        float e2 = fmaf(ex, ex, fmaf(ey, ey, ez * ez));
                        k1 = __float_as_uint(e2);
                        j1 = t1 * 32 + w;
                    } else { k1 = EMPTY_BITS; j1 = -1; }
                }
                unsigned resv = EMPTY_BITS; int resj = 0;
                for (int it = 0; it < k; ++it) {
                    unsigned lmin = (k1 < k0) ? k1 : k0;
                    int      lj   = (k1 < k0) ? j1 : j0;
                    unsigned gm  = __reduce_min_sync(0xffffffffu, lmin);
                    unsigned gcj = (lmin == gm) ? (unsigned)lj : 0xFFFFFFFFu;
                    unsigned gj  = __reduce_min_sync(0xffffffffu, gcj);
                    resv = gm; resj = (int)gj;
                    if (j0 == (int)gj) k0 = EMPTY_BITS;
                    if (j1 == (int)gj) k1 = EMPTY_BITS;
                }
                if (lane == w) {
                    if (fromA) { va0 = resv; ia0 = resj; }
                    else       { vb0 = resv; ib0 = resj; }
                }
            }
        }
    }

    if (lane < KNB) {
        float d2 = __uint_as_float(rvb);
        float dv = (d2 > 1e30f) ? BIGD : sqrtf(d2 + 1e-6f);
        dist_out[lane] = dv;
        idx_out[lane]  = (float)rj;
    }
}

// ---------------------------------------------------------------------------
extern "C" void kernel_launch(void* const* d_in, const int* in_sizes, int n_in,
                              void* d_out, int out_size) {
    const float* coords = (const float*)d_in[0];   // (2,256,12,3) f32
    const int*   mask   = (const int*)d_in[1];     // (2,256) i32
    const float* emb    = (const float*)d_in[2];   // (12,32) f32
    const float* scale  = (const float*)d_in[3];   // (1,1,32) f32
    const float* shift  = (const float*)d_in[4];   // (1,1,32) f32
    float* out = (float*)d_out;

    prep_kernel<<<PREP_BLOCKS, 256>>>(coords, mask, emb, scale, shift);

    int nblocks = NROWS / WARPS;                   // 1536
    knn_kernel<<<nblocks, THR>>>(coords, emb, out);
}